// round 8
// baseline (speedup 1.0000x reference)
#include <cuda_runtime.h>

// DeconvDft2dLayer == per-row 512-pt circular deconvolution:
//   y[row,:] = ifft( M(k) * fft(x[row,:]) ),  M(k) = 1/|H(k)|^4 (real),
//   H(k) = sum_{n=0}^{7} w[n] e^{-2pi i k n/512}.
// Two real rows packed per complex FFT (M real => exact). Each thread runs
// TWO independent FFTs (4 rows) for ILP. Radix-8 Stockham, ping-pong padded
// smem (4 syncs total), log-depth twiddle power chains shared by both FFTs,
// M computed per-thread in registers: H(u+64j) = DFT8_j( w[n] * w1^n ).
// Single kernel launch.

#define NW 512
#define THREADS 64
#define PAD2 (NW + (NW >> 3))   // 576 float2 per FFT buffer

__device__ __forceinline__ float2 cmulf(float2 a, float2 b) {
    return make_float2(a.x * b.x - a.y * b.y, a.x * b.y + a.y * b.x);
}

// In-register radix-8 DFT. Forward e^{-i...}; INV flips sign.
template<bool INV>
__device__ __forceinline__ void dft8(float* ar, float* ai) {
    const float s = INV ? 1.0f : -1.0f;
    const float C = 0.70710678118654752440f;

    float e0r = ar[0] + ar[4], e0i = ai[0] + ai[4];
    float e1r = ar[0] - ar[4], e1i = ai[0] - ai[4];
    float e2r = ar[2] + ar[6], e2i = ai[2] + ai[6];
    float e3r = ar[2] - ar[6], e3i = ai[2] - ai[6];
    float E0r = e0r + e2r, E0i = e0i + e2i;
    float E2r = e0r - e2r, E2i = e0i - e2i;
    float E1r = e1r - s * e3i, E1i = e1i + s * e3r;
    float E3r = e1r + s * e3i, E3i = e1i - s * e3r;

    float o0r = ar[1] + ar[5], o0i = ai[1] + ai[5];
    float o1r = ar[1] - ar[5], o1i = ai[1] - ai[5];
    float o2r = ar[3] + ar[7], o2i = ai[3] + ai[7];
    float o3r = ar[3] - ar[7], o3i = ai[3] - ai[7];
    float O0r = o0r + o2r, O0i = o0i + o2i;
    float O2r = o0r - o2r, O2i = o0i - o2i;
    float O1r = o1r - s * o3i, O1i = o1i + s * o3r;
    float O3r = o1r + s * o3i, O3i = o1i - s * o3r;

    float w1r = C * (O1r - s * O1i), w1i = C * (s * O1r + O1i);
    float w2r = -s * O2i,             w2i = s * O2r;
    float w3r = C * (-O3r - s * O3i), w3i = C * (s * O3r - O3i);

    ar[0] = E0r + O0r; ai[0] = E0i + O0i;
    ar[4] = E0r - O0r; ai[4] = E0i - O0i;
    ar[1] = E1r + w1r; ai[1] = E1i + w1i;
    ar[5] = E1r - w1r; ai[5] = E1i - w1i;
    ar[2] = E2r + w2r; ai[2] = E2i + w2i;
    ar[6] = E2r - w2r; ai[6] = E2i - w2i;
    ar[3] = E3r + w3r; ai[3] = E3i + w3i;
    ar[7] = E3r - w3r; ai[7] = E3i - w3i;
}

// Twiddle both batched FFTs by W^j (conj for INV) and store; powers built
// once with a log-depth chain (depth 3) and shared by A and B.
template<bool INV>
__device__ __forceinline__ void tw_store2(float2* __restrict__ bufA,
                                          float2* __restrict__ bufB,
                                          const float* ar, const float* ai,
                                          const float* br, const float* bi,
                                          float2 w, int base, int stride) {
    bufA[base] = make_float2(ar[0], ai[0]);
    bufB[base] = make_float2(br[0], bi[0]);
    float2 cs[8];
    cs[1] = w;
    cs[2] = cmulf(w, w);
    cs[3] = cmulf(cs[2], w);
    cs[4] = cmulf(cs[2], cs[2]);
    cs[5] = cmulf(cs[4], w);
    cs[6] = cmulf(cs[4], cs[2]);
    cs[7] = cmulf(cs[4], cs[3]);
#pragma unroll
    for (int j = 1; j < 8; j++) {
        float cr = cs[j].x;
        float ci = INV ? -cs[j].y : cs[j].y;
        int idx = base + stride * j;
        bufA[idx] = make_float2(ar[j] * cr - ai[j] * ci, ar[j] * ci + ai[j] * cr);
        bufB[idx] = make_float2(br[j] * cr - bi[j] * ci, br[j] * ci + bi[j] * cr);
    }
}

__device__ __forceinline__ void load2(float* ar, float* ai, float* br, float* bi,
                                      const float2* __restrict__ bufA,
                                      const float2* __restrict__ bufB, int ub) {
#pragma unroll
    for (int j = 0; j < 8; j++) {
        float2 va = bufA[ub + 72 * j];
        float2 vb = bufB[ub + 72 * j];
        ar[j] = va.x; ai[j] = va.y;
        br[j] = vb.x; bi[j] = vb.y;
    }
}

__global__ void __launch_bounds__(THREADS, 12)
fft_conv_kernel(const float* __restrict__ x, const float* __restrict__ w,
                float* __restrict__ out) {
    __shared__ float2 sP[2][PAD2];   // ping buffers (FFT A, FFT B)
    __shared__ float2 sQ[2][PAD2];   // pong buffers

    int u = threadIdx.x;
    int ub = u + (u >> 3);
    int p = u >> 3, q = u & 7;

    float2 w1, w2;
    sincospif(-(float)u * (1.0f / 256.0f), &w1.y, &w1.x);   // e^{-2pi i u/512}
    sincospif(-(float)p * (1.0f / 32.0f),  &w2.y, &w2.x);   // e^{-2pi i p/64}

    int base = blockIdx.x * (4 * NW);   // 4 rows per block
    const float* xA0 = x + base;
    const float* xA1 = xA0 + NW;
    const float* xB0 = xA0 + 2 * NW;
    const float* xB1 = xA0 + 3 * NW;

    float ar[8], ai[8], br[8], bi[8];
#pragma unroll
    for (int j = 0; j < 8; j++) {
        int g = u + 64 * j;
        ar[j] = __ldg(xA0 + g);
        ai[j] = __ldg(xA1 + g);
        br[j] = __ldg(xB0 + g);
        bi[j] = __ldg(xB1 + g);
    }

    // ---- forward ----
    dft8<false>(ar, ai);
    dft8<false>(br, bi);
    tw_store2<false>(sP[0], sP[1], ar, ai, br, bi, w1, 9 * u, 1);
    __syncthreads();

    load2(ar, ai, br, bi, sP[0], sP[1], ub);
    dft8<false>(ar, ai);
    dft8<false>(br, bi);
    tw_store2<false>(sQ[0], sQ[1], ar, ai, br, bi, w2, q + 72 * p, 9);
    __syncthreads();

    load2(ar, ai, br, bi, sQ[0], sQ[1], ub);
    dft8<false>(ar, ai);
    dft8<false>(br, bi);                 // natural order: reg j = bin u+64j

    // ---- fused M: H(u+64j) = DFT8_j( w[n] * w1^n ),  M = 1/(|H|^2)^2/512 ----
    {
        float vr[8], vi[8];
        vr[0] = __ldg(w + 0);
        vi[0] = 0.0f;
        float pr = w1.x, pi = w1.y;       // serial chain: off critical path
#pragma unroll
        for (int n = 1; n < 8; n++) {
            float wt = __ldg(w + n);
            vr[n] = wt * pr;
            vi[n] = wt * pi;
            if (n < 7) {
                float nr = pr * w1.x - pi * w1.y;
                float ni = pr * w1.y + pi * w1.x;
                pr = nr; pi = ni;
            }
        }
        dft8<false>(vr, vi);              // vr[j]+i vi[j] = H(u + 64j)
#pragma unroll
        for (int j = 0; j < 8; j++) {
            float pw = vr[j] * vr[j] + vi[j] * vi[j];    // |H|^2
            float m = 1.0f / (pw * pw * (float)NW);      // ifft 1/N folded in
            ar[j] *= m; ai[j] *= m;
            br[j] *= m; bi[j] *= m;
        }
    }

    // ---- inverse ---- (stores to sP: every thread's read of sP happened
    // before the sync after the sQ store, so no extra sync needed)
    dft8<true>(ar, ai);
    dft8<true>(br, bi);
    tw_store2<true>(sP[0], sP[1], ar, ai, br, bi, w1, 9 * u, 1);
    __syncthreads();

    load2(ar, ai, br, bi, sP[0], sP[1], ub);
    dft8<true>(ar, ai);
    dft8<true>(br, bi);
    tw_store2<true>(sQ[0], sQ[1], ar, ai, br, bi, w2, q + 72 * p, 9);
    __syncthreads();

    load2(ar, ai, br, bi, sQ[0], sQ[1], ub);
    dft8<true>(ar, ai);
    dft8<true>(br, bi);

    float* oA0 = out + base;
    float* oA1 = oA0 + NW;
    float* oB0 = oA0 + 2 * NW;
    float* oB1 = oA0 + 3 * NW;
#pragma unroll
    for (int j = 0; j < 8; j++) {
        int g = u + 64 * j;
        oA0[g] = ar[j];
        oA1[g] = ai[j];
        oB0[g] = br[j];
        oB1[g] = bi[j];
    }
}

extern "C" void kernel_launch(void* const* d_in, const int* in_sizes, int n_in,
                              void* d_out, int out_size) {
    const float* x = (const float*)d_in[0];
    const float* w = (const float*)d_in[1];
    if (n_in >= 2 && in_sizes[0] < in_sizes[1]) {   // defensive: x is the big one
        const float* t = x; x = w; w = t;
    }
    float* out = (float*)d_out;

    int rows = out_size / NW;        // 16384
    int blocks = rows / 4;           // 4096 (4 rows per block)
    fft_conv_kernel<<<blocks, THREADS>>>(x, w, out);
}